// round 8
// baseline (speedup 1.0000x reference)
#include <cuda_runtime.h>
#include <cuda_fp16.h>
#include <cstdint>

#define BATCH 16384

// ---------------- static scratch (device globals; no allocations) ----------------
__device__ float g_bufA[(long long)BATCH * 6000];
__device__ float g_bufB[(long long)BATCH * 3000];
__device__ float g_bufC[(long long)BATCH * 1875];
__device__ float g_x1 [(long long)BATCH * 2250];
__device__ float g_x2 [(long long)BATCH * 3750];
// half (hi,lo) interleaved planes for tensor-core consumers
__device__ __half2 g_hX[(long long)BATCH * 3750];
__device__ __half2 g_hB[(long long)BATCH * 3000];
__device__ __half2 g_hC[(long long)BATCH * 1875];
__device__ __half2 g_hW[606080];

__device__ __forceinline__ __half2 split2(float v) {
    const __half hi = __float2half_rn(v);
    return __halves2half2(hi, __float2half_rn(v - __half2float(hi)));
}

// Packed fp32x2 FMA (Blackwell FFMA2).
__device__ __forceinline__ void ffma2(float2& d, const float2& a, const float2& b) {
    unsigned long long& dd = reinterpret_cast<unsigned long long&>(d);
    const unsigned long long& aa = reinterpret_cast<const unsigned long long&>(a);
    const unsigned long long& bb = reinterpret_cast<const unsigned long long&>(b);
    asm("fma.rn.f32x2 %0, %1, %2, %0;" : "+l"(dd) : "l"(aa), "l"(bb));
}

// ---------------- weight pre-split -------------------------------------------
__global__ void split_w(const float* __restrict__ w, __half2* __restrict__ o, int n) {
    const int i = blockIdx.x * 256 + threadIdx.x;
    if (i < n) o[i] = split2(w[i]);
}

// ============================================================================
// Streaming semi-linear: A [M][K] contiguous -> Out [M][N] contiguous.
// Fully coalesced float4 I/O; per-thread row compute; optional relu/half out.
// ============================================================================
template<int N,int K,int RELU,int HOUT>
__global__ void __launch_bounds__(256)
slfast(const float* __restrict__ A, const float* __restrict__ W,
       const float* __restrict__ bias, float* __restrict__ Out,
       __half2* __restrict__ hOut)
{
    constexpr int BM   = 256;
    constexpr int SAST = (K % 2 == 1) ? K : K + 1;   // odd word stride -> conflict-free
    constexpr int SOST = (N % 2 == 1) ? N : N + 1;

    __shared__ float sA[BM * SAST];
    __shared__ float sO[BM * SOST];
    __shared__ float sWb[K * N + N];

    const int tid = threadIdx.x;
    const long long base = (long long)blockIdx.x * BM;

    // weights (sW[k*N+n] = W[n*K+k]) + bias
#pragma unroll 2
    for (int i = tid; i < K * N + N; i += 256)
        sWb[i] = (i < K * N) ? W[(i % N) * K + (i / N)] : bias[i - K * N];

    // A chunk: BM*K contiguous floats, float4 loads
    {
        const float4* Ag = (const float4*)(A + base * K);
        constexpr int NV = BM * K / 4;
        for (int i = tid; i < NV; i += 256) {
            const float4 v = Ag[i];
            const int j = 4 * i;
            sA[((j    ) / K) * SAST + ((j    ) % K)] = v.x;
            sA[((j + 1) / K) * SAST + ((j + 1) % K)] = v.y;
            sA[((j + 2) / K) * SAST + ((j + 2) % K)] = v.z;
            sA[((j + 3) / K) * SAST + ((j + 3) % K)] = v.w;
        }
    }
    __syncthreads();

    // compute one row per thread
    {
        float acc[N];
#pragma unroll
        for (int n = 0; n < N; n++) acc[n] = sWb[K * N + n];
        const float* ar = &sA[tid * SAST];
#pragma unroll
        for (int k = 0; k < K; k++) {
            const float a = ar[k];
#pragma unroll
            for (int n = 0; n < N; n++)
                acc[n] = fmaf(a, sWb[k * N + n], acc[n]);
        }
        float* orow = &sO[tid * SOST];
#pragma unroll
        for (int n = 0; n < N; n++)
            orow[n] = RELU ? fmaxf(acc[n], 0.0f) : acc[n];
    }
    __syncthreads();

    // coalesced store (fp32 + optional half2 plane)
    {
        float4* Og = (float4*)(Out + base * N);
        constexpr int NV = BM * N / 4;
        for (int i = tid; i < NV; i += 256) {
            const int j = 4 * i;
            float4 v;
            v.x = sO[((j    ) / N) * SOST + ((j    ) % N)];
            v.y = sO[((j + 1) / N) * SOST + ((j + 1) % N)];
            v.z = sO[((j + 2) / N) * SOST + ((j + 2) % N)];
            v.w = sO[((j + 3) / N) * SOST + ((j + 3) % N)];
            Og[i] = v;
            if (HOUT) {
                __half2 h[4];
                h[0] = split2(v.x); h[1] = split2(v.y);
                h[2] = split2(v.z); h[3] = split2(v.w);
                *(uint4*)(hOut + base * N + j) = *(const uint4*)h;
            }
        }
    }
}

// ============================================================================
// SIMT fp32 GEMM (R3 version, proven) + optional half-plane output
// (used for the 3 small stage-0 convs)
// ============================================================================
template<int MODE,int KH,int BM,int BN,int BK,int TM,int TN,int N,int K,int RELU,int ACCUM,int HOUT>
__global__ void __launch_bounds__((BM/TM)*(BN/TN), 2)
gemm(const float* __restrict__ A, const float* __restrict__ W,
     const float* __restrict__ bias, float* __restrict__ Out, __half2* __restrict__ hOut,
     int IH, int IW, int PH, int SP, int OW, int abstride)
{
    constexpr int NT    = (BM/TM)*(BN/TN);
    constexpr int KITER = (K + BK - 1) / BK;
    constexpr bool KG   = (K % BK) != 0;
    constexpr bool NG   = (N % BN) != 0;
    constexpr int ROWS  = (BM > NT) ? BM/NT : 1;
    constexpr int KSL   = (NT > BM) ? NT/BM : 1;
    constexpr int AJ    = BK / KSL;
    static_assert(BK % KSL == 0, "");
    static_assert(TN % 2 == 0, "");

    __shared__ __align__(16) float sA[BK][2*BM];
    __shared__ __align__(16) float sB[BK][BN + 4];

    const int tid = threadIdx.x;
    const int m0  = blockIdx.x * BM;
    const int n0  = blockIdx.y * BN;

    const int a_k0 = (NT > BM) ? (tid / BM) : 0;
    const float* Abase[ROWS];
    int oh_[ROWS], aml[ROWS];
    const int IHW = IH * IW;
#pragma unroll
    for (int r = 0; r < ROWS; r++) {
        const int ml = (NT >= BM) ? (tid % BM) : (tid + r * NT);
        aml[r] = ml;
        const int m = m0 + ml;
        const int b = m / SP;
        const int s = m - b * SP;
        if (MODE == 0) {
            const int oh = s / OW;
            oh_[r] = oh;
            Abase[r] = A + (long long)b * abstride + (s - oh * OW);
        } else {
            oh_[r] = 0;
            Abase[r] = A + (long long)b * abstride + (long long)s * K;
        }
    }

    const int tn = tid % (BN/TN);
    const int tm = tid / (BN/TN);

    float2 acc[TM][TN/2];
#pragma unroll
    for (int i = 0; i < TM; i++)
#pragma unroll
        for (int j = 0; j < TN/2; j++) acc[i][j] = make_float2(0.f, 0.f);

    for (int kt = 0; kt < KITER; kt++) {
        const int k0 = kt * BK;
#pragma unroll
        for (int r = 0; r < ROWS; r++) {
#pragma unroll
            for (int j = 0; j < AJ; j++) {
                const int kl = a_k0 + KSL * j;
                const int k  = k0 + kl;
                float v = 0.0f;
                if (!KG || k < K) {
                    if (MODE == 0) {
                        const int ic = k / KH;
                        const int kh = k - ic * KH;
                        const int ih = oh_[r] + kh - PH;
                        if ((unsigned)ih < (unsigned)IH)
                            v = Abase[r][ic * IHW + ih * IW];
                    } else {
                        v = Abase[r][k];
                    }
                }
                *(float2*)&sA[kl][2 * aml[r]] = make_float2(v, v);
            }
        }
        constexpr int BTOT = BK * BN;
        constexpr int BIT  = (BTOT + NT - 1) / NT;
#pragma unroll
        for (int t = 0; t < BIT; t++) {
            const int idx = tid + t * NT;
            if (BTOT % NT == 0 || idx < BTOT) {
                const int kl = idx % BK;
                const int n  = idx / BK;
                const int k  = k0 + kl;
                const int nn = n0 + n;
                float v = 0.0f;
                if ((!KG || k < K) && (!NG || nn < N)) v = W[nn * K + k];
                sB[kl][n] = v;
            }
        }
        __syncthreads();

#pragma unroll
        for (int kk = 0; kk < BK; kk++) {
            float2 a2[TM], b2[TN/2];
            {
                const float4* pa = (const float4*)&sA[kk][2 * tm * TM];
#pragma unroll
                for (int q = 0; q < TM/2; q++) {
                    const float4 t4 = pa[q];
                    a2[2*q]   = make_float2(t4.x, t4.y);
                    a2[2*q+1] = make_float2(t4.z, t4.w);
                }
            }
            if constexpr (TN % 4 == 0) {
                const float4* pb = (const float4*)&sB[kk][tn * TN];
#pragma unroll
                for (int q = 0; q < TN/4; q++) {
                    const float4 t4 = pb[q];
                    b2[2*q]   = make_float2(t4.x, t4.y);
                    b2[2*q+1] = make_float2(t4.z, t4.w);
                }
            } else {
                const float2* pb = (const float2*)&sB[kk][tn * TN];
#pragma unroll
                for (int q = 0; q < TN/2; q++) b2[q] = pb[q];
            }
#pragma unroll
            for (int i = 0; i < TM; i++)
#pragma unroll
                for (int j = 0; j < TN/2; j++)
                    ffma2(acc[i][j], a2[i], b2[j]);
        }
        __syncthreads();
    }

#pragma unroll
    for (int i = 0; i < TM; i++) {
        const int m = m0 + tm * TM + i;
        const int b = m / SP;
        const int s = m - b * SP;
#pragma unroll
        for (int j = 0; j < TN/2; j++) {
#pragma unroll
            for (int h = 0; h < 2; h++) {
                const int n = n0 + tn * TN + 2*j + h;
                if (!NG || n < N) {
                    float v = (h ? acc[i][j].y : acc[i][j].x) + bias[n];
                    if (RELU) v = fmaxf(v, 0.0f);
                    long long o;
                    if (MODE == 0) o = (long long)b * (N * SP) + (long long)n * SP + s;
                    else           o = (long long)b * (SP * N) + (long long)s * N + n;
                    if (ACCUM) v += Out[o];
                    Out[o] = v;
                    if (HOUT) hOut[o] = split2(v);
                }
            }
        }
    }
}

// ============================================================================
// Tensor-core conv GEMM v2 (R6, proven): pre-split half2 inputs, reg prefetch.
// ============================================================================
__device__ __forceinline__ void mma16816(float* c, const uint32_t* a, const uint32_t* b) {
    asm volatile(
        "mma.sync.aligned.m16n8k16.row.col.f32.f16.f16.f32 "
        "{%0,%1,%2,%3}, {%4,%5,%6,%7}, {%8,%9}, {%0,%1,%2,%3};"
        : "+f"(c[0]), "+f"(c[1]), "+f"(c[2]), "+f"(c[3])
        : "r"(a[0]), "r"(a[1]), "r"(a[2]), "r"(a[3]), "r"(b[0]), "r"(b[1]));
}

template<int KH,int N,int K,int ACCUM,int HOUT,int NB>
__global__ void __launch_bounds__(128, 4)
tconv(const __half2* __restrict__ Ah, const __half2* __restrict__ Wh,
      const float* __restrict__ bias, float* __restrict__ Out, __half2* __restrict__ hOut,
      int IH, int IW, int PH, int SP, int OW, int abstride)
{
    constexpr int BM = 64, BN = 64, BK = 32;
    constexpr int KITER = (K + BK - 1) / BK;
    constexpr int PAD   = 38;
    __shared__ __align__(16) __half sAhi[BM][PAD];
    __shared__ __align__(16) __half sAlo[BM][PAD];
    __shared__ __align__(16) __half sBhi[BN][PAD];
    __shared__ __align__(16) __half sBlo[BN][PAD];

    const int tid  = threadIdx.x;
    const int nb   = (int)(blockIdx.x % NB);
    const int mb   = (int)(blockIdx.x / NB);
    const int m0   = mb * BM;
    const int n0   = nb * BN;
    const int IHW  = IH * IW;

    const int arow = tid & 63;
    const int ak0  = tid >> 6;
    const int am   = m0 + arow;
    const int ab   = am / SP;
    const int as   = am - ab * SP;
    const int aoh  = as / OW;
    const __half2* Abase = Ah + (long long)ab * abstride + (as - aoh * OW);

    const int bkl = tid & 31;
    const int bn0 = tid >> 5;

    const int warp = tid >> 5, lane = tid & 31;
    const int wm = (warp & 1) * 32;
    const int wn = (warp >> 1) * 32;
    const int gr = lane >> 2;
    const int gc = lane & 3;

    __half2 aR[16], bR[16];
    const __half2 Z2 = __float2half2_rn(0.0f);

    auto prefetch = [&](int kt) {
        const int k0 = kt * BK;
#pragma unroll
        for (int t = 0; t < 16; t++) {
            const int k = k0 + ak0 + 2 * t;
            __half2 v = Z2;
            if (K % BK == 0 || k < K) {
                const int ic = k / KH;
                const int kh = k - ic * KH;
                const int ih = aoh + kh - PH;
                if ((unsigned)ih < (unsigned)IH)
                    v = Abase[ic * IHW + ih * IW];
            }
            aR[t] = v;
        }
        const int kB = k0 + bkl;
#pragma unroll
        for (int t = 0; t < 16; t++) {
            const int nn = n0 + bn0 + 4 * t;
            __half2 v = Z2;
            if ((K % BK == 0 || kB < K) && (N % BN == 0 || nn < N))
                v = Wh[(long long)nn * K + kB];
            bR[t] = v;
        }
    };

    auto stage = [&]() {
#pragma unroll
        for (int t = 0; t < 16; t++) {
            const int kl = ak0 + 2 * t;
            sAhi[arow][kl] = __low2half(aR[t]);
            sAlo[arow][kl] = __high2half(aR[t]);
        }
#pragma unroll
        for (int t = 0; t < 16; t++) {
            const int nl = bn0 + 4 * t;
            sBhi[nl][bkl] = __low2half(bR[t]);
            sBlo[nl][bkl] = __high2half(bR[t]);
        }
    };

    float acc[2][4][4];
#pragma unroll
    for (int i = 0; i < 2; i++)
#pragma unroll
        for (int j = 0; j < 4; j++)
#pragma unroll
            for (int q = 0; q < 4; q++) acc[i][j][q] = 0.0f;

    prefetch(0);
    for (int kt = 0; kt < KITER; kt++) {
        stage();
        __syncthreads();
        if (kt + 1 < KITER) prefetch(kt + 1);
#pragma unroll
        for (int ck = 0; ck < BK / 16; ck++) {
            const int kb = ck * 16 + 2 * gc;
            uint32_t ahi[2][4], alo[2][4], bhi[4][2], blo[4][2];
#pragma unroll
            for (int ms = 0; ms < 2; ms++) {
                const int r0 = wm + ms * 16 + gr;
                ahi[ms][0] = *(const uint32_t*)&sAhi[r0    ][kb    ];
                ahi[ms][1] = *(const uint32_t*)&sAhi[r0 + 8][kb    ];
                ahi[ms][2] = *(const uint32_t*)&sAhi[r0    ][kb + 8];
                ahi[ms][3] = *(const uint32_t*)&sAhi[r0 + 8][kb + 8];
                alo[ms][0] = *(const uint32_t*)&sAlo[r0    ][kb    ];
                alo[ms][1] = *(const uint32_t*)&sAlo[r0 + 8][kb    ];
                alo[ms][2] = *(const uint32_t*)&sAlo[r0    ][kb + 8];
                alo[ms][3] = *(const uint32_t*)&sAlo[r0 + 8][kb + 8];
            }
#pragma unroll
            for (int ns = 0; ns < 4; ns++) {
                const int nr = wn + ns * 8 + gr;
                bhi[ns][0] = *(const uint32_t*)&sBhi[nr][kb    ];
                bhi[ns][1] = *(const uint32_t*)&sBhi[nr][kb + 8];
                blo[ns][0] = *(const uint32_t*)&sBlo[nr][kb    ];
                blo[ns][1] = *(const uint32_t*)&sBlo[nr][kb + 8];
            }
#pragma unroll
            for (int ms = 0; ms < 2; ms++)
#pragma unroll
                for (int ns = 0; ns < 4; ns++) {
                    mma16816(acc[ms][ns], ahi[ms], bhi[ns]);
                    mma16816(acc[ms][ns], ahi[ms], blo[ns]);
                    mma16816(acc[ms][ns], alo[ms], bhi[ns]);
                }
        }
        __syncthreads();
    }

#pragma unroll
    for (int ms = 0; ms < 2; ms++) {
        const int mr0 = m0 + wm + ms * 16 + gr;
#pragma unroll
        for (int half = 0; half < 2; half++) {
            const int m = mr0 + half * 8;
            const int b = m / SP;
            const int s = m - b * SP;
            const long long obase = (long long)b * (N * SP) + s;
#pragma unroll
            for (int ns = 0; ns < 4; ns++) {
                const int n = n0 + wn + ns * 8 + 2 * gc;
#pragma unroll
                for (int e = 0; e < 2; e++) {
                    const int nn = n + e;
                    if (N % BN == 0 || nn < N) {
                        float v = acc[ms][ns][half * 2 + e] + bias[nn];
                        const long long o = obase + (long long)nn * SP;
                        if (ACCUM) v += Out[o];
                        Out[o] = v;
                        if (HOUT) hOut[o] = split2(v);
                    }
                }
            }
        }
    }
}

// ---------------- host-side typed launchers ----------------
template<int KH,int BN,int BK,int TM,int TN,int N,int K,int ACCUM,int HOUT>
static void conv(const float* A, const float* W, const float* b, float* O, __half2* hO,
                 int IH, int IW, int PH)
{
    constexpr int BM = 128;
    const int OH = IH + 2*PH - KH + 1, OW = IW, SP = OH * OW;
    const long long M = (long long)BATCH * SP;
    dim3 g((unsigned)(M / BM), (N + BN - 1) / BN);
    gemm<0,KH,BM,BN,BK,TM,TN,N,K,0,ACCUM,HOUT><<<g, (BM/TM)*(BN/TN)>>>(
        A, W, b, O, hO, IH, IW, PH, SP, OW, (K/KH)*IH*IW);
}

template<int KH,int N,int K,int ACCUM,int HOUT>
static void tconv_l(const __half2* A, const __half2* W, const float* b, float* O,
                    __half2* hO, int IH, int IW, int PH)
{
    constexpr int NB = (N + 63) / 64;
    const int OH = IH + 2*PH - KH + 1, OW = IW, SP = OH * OW;
    const long long M = (long long)BATCH * SP;
    dim3 g((unsigned)((M / 64) * NB));
    tconv<KH,N,K,ACCUM,HOUT,NB><<<g, 128>>>(A, W, b, O, hO, IH, IW, PH, SP, OW, (K/KH)*IH*IW);
}

template<int N,int K,int RELU,int HOUT>
static void sl2(const float* A, const float* W, const float* b, float* O, __half2* hO, int SP)
{
    const long long M = (long long)BATCH * SP;
    slfast<N,K,RELU,HOUT><<<(unsigned)(M / 256), 256>>>(A, W, b, O, hO);
}

extern "C" void kernel_launch(void* const* d_in, const int* in_sizes, int n_in,
                              void* d_out, int out_size)
{
    (void)in_sizes; (void)n_in; (void)out_size;
    const float* x    = (const float*)d_in[0];
    const float* w0a  = (const float*)d_in[1];  const float* b0a  = (const float*)d_in[2];
    const float* wl0  = (const float*)d_in[3];  const float* bl0  = (const float*)d_in[4];
    const float* w0b  = (const float*)d_in[5];  const float* b0b  = (const float*)d_in[6];
    const float* w0c  = (const float*)d_in[7];  const float* b0c  = (const float*)d_in[8];
    const float* wr0  = (const float*)d_in[9];  const float* br0  = (const float*)d_in[10];
    const float* w1   = (const float*)d_in[11]; const float* b1   = (const float*)d_in[12];
    const float* wl1  = (const float*)d_in[13]; const float* bl1  = (const float*)d_in[14];
    const float* w2   = (const float*)d_in[15]; const float* b2   = (const float*)d_in[16];
    const float* wa   = (const float*)d_in[17]; const float* ba   = (const float*)d_in[18];
    const float* wra  = (const float*)d_in[19]; const float* bra  = (const float*)d_in[20];
    const float* w0   = (const float*)d_in[21]; const float* b0   = (const float*)d_in[22];
    const float* wl2  = (const float*)d_in[23]; const float* bl2  = (const float*)d_in[24];
    const float* w0b2 = (const float*)d_in[25]; const float* b0b2 = (const float*)d_in[26];
    const float* w0c2 = (const float*)d_in[27]; const float* b0c2 = (const float*)d_in[28];
    const float* wr02 = (const float*)d_in[29]; const float* br02 = (const float*)d_in[30];
    float* out = (float*)d_out;

    float *A, *Bb, *C, *x1, *x2;
    __half2 *hX, *hB, *hC, *hW;
    cudaGetSymbolAddress((void**)&A,  g_bufA);
    cudaGetSymbolAddress((void**)&Bb, g_bufB);
    cudaGetSymbolAddress((void**)&C,  g_bufC);
    cudaGetSymbolAddress((void**)&x1, g_x1);
    cudaGetSymbolAddress((void**)&x2, g_x2);
    cudaGetSymbolAddress((void**)&hX, g_hX);
    cudaGetSymbolAddress((void**)&hB, g_hB);
    cudaGetSymbolAddress((void**)&hC, g_hC);
    cudaGetSymbolAddress((void**)&hW, g_hW);

    // ---- weight pre-split (hi,lo) for the 6 heavy layers ----
    __half2* hw1   = hW;            // 3750
    __half2* hw2   = hW + 3750;     // 18750
    __half2* hwa   = hW + 22500;    // 9375
    __half2* hw0   = hW + 31875;    // 75000
    __half2* hw0b2 = hW + 106875;   // 307200
    __half2* hw0c2 = hW + 414075;   // 192000
    split_w<<<(3750+255)/256,   256>>>(w1,   hw1,   3750);
    split_w<<<(18750+255)/256,  256>>>(w2,   hw2,   18750);
    split_w<<<(9375+255)/256,   256>>>(wa,   hwa,   9375);
    split_w<<<(75000+255)/256,  256>>>(w0,   hw0,   75000);
    split_w<<<(307200+255)/256, 256>>>(w0b2, hw0b2, 307200);
    split_w<<<(192000+255)/256, 256>>>(w0c2, hw0c2, 192000);

    // ---- stage 0 ----
    conv<3,  8, 4, 8,2,   5,  3, 0,0>(x,  w0a,  b0a,  A,  nullptr, 5, 27, 1);
    sl2 <18, 27, 1, 0>(A,  wl0, bl0, Bb, nullptr, 25);               // relu
    conv<3, 32,15, 8,4,  25, 15, 0,0>(Bb, w0b,  b0b,  x1, nullptr, 5, 18, 1);
    sl2 <18, 27, 0, 0>(x,  wr0, br0, C,  nullptr, 5);
    conv<1, 32, 1, 8,4,  25,  1, 1,1>(C,  w0c,  b0c,  x1, hX,      5, 18, 0); // final x1 + half

    // ---- stage 1 ----
    tconv_l<2,  75,  50, 0,0>(hX, hw1, b1, A, nullptr, 5, 18, 0);
    sl2 <10, 18, 1, 1>(A,  wl1, bl1, Bb, hB, 300);                   // relu + half
    tconv_l<2, 125, 150, 0,0>(hB, hw2, b2, x2, nullptr, 4, 10, 0);
    sl2 <10, 18, 0, 1>(x1, wra, bra, C,  hC, 125);                   // + half
    tconv_l<3, 125,  75, 1,1>(hC, hwa, ba, x2, hX, 5, 10, 0);        // += y, x2 + half

    // ---- stage 2 ----
    tconv_l<2, 300, 250, 0,0>(hX, hw0, b0, A, nullptr, 3, 10, 0);
    sl2 < 5, 10, 1, 1>(A,  wl2, bl2, Bb, hB, 600);                   // relu + half
    tconv_l<2, 512, 600, 0,0>(hB, hw0b2, b0b2, out, nullptr, 2, 5, 0);
    sl2 < 5, 10, 0, 1>(x2, wr02, br02, C,  hC, 375);                 // + half
    tconv_l<3, 512, 375, 1,0>(hC, hw0c2, b0c2, out, nullptr, 3, 5, 0);
}

// round 10
// speedup vs baseline: 1.3608x; 1.3608x over previous
#include <cuda_runtime.h>
#include <cuda_fp16.h>
#include <cstdint>

#define BATCH 16384

// ---------------- static scratch (device globals; no allocations) ----------------
__device__ float g_bufA[(long long)BATCH * 6000];
__device__ float g_bufB[(long long)BATCH * 3000];
__device__ float g_bufC[(long long)BATCH * 1875];
__device__ float g_x1 [(long long)BATCH * 2250];
__device__ float g_x2 [(long long)BATCH * 3750];
// half (hi,lo) interleaved planes for tensor-core consumers
__device__ __half2 g_hX[(long long)BATCH * 3750];
__device__ __half2 g_hB[(long long)BATCH * 3000];
__device__ __half2 g_hC[(long long)BATCH * 1875];
__device__ __half2 g_hW[606080];

__device__ __forceinline__ __half2 split2(float v) {
    const __half hi = __float2half_rn(v);
    return __halves2half2(hi, __float2half_rn(v - __half2float(hi)));
}

// Packed fp32x2 FMA (Blackwell FFMA2).
__device__ __forceinline__ void ffma2(float2& d, const float2& a, const float2& b) {
    unsigned long long& dd = reinterpret_cast<unsigned long long&>(d);
    const unsigned long long& aa = reinterpret_cast<const unsigned long long&>(a);
    const unsigned long long& bb = reinterpret_cast<const unsigned long long&>(b);
    asm("fma.rn.f32x2 %0, %1, %2, %0;" : "+l"(dd) : "l"(aa), "l"(bb));
}

// ---------------- weight pre-split (single launch, 6 weights) ----------------
__global__ void split_w6(const float* __restrict__ w1, const float* __restrict__ w2,
                         const float* __restrict__ wa, const float* __restrict__ w0,
                         const float* __restrict__ wb2, const float* __restrict__ wc2,
                         __half2* __restrict__ o)
{
    const int i = blockIdx.x * 256 + threadIdx.x;
    if (i >= 606075) return;
    const float* s; int off;
    if      (i <   3750) { s = w1;  off = 0; }
    else if (i <  22500) { s = w2;  off = 3750; }
    else if (i <  31875) { s = wa;  off = 22500; }
    else if (i < 106875) { s = w0;  off = 31875; }
    else if (i < 414075) { s = wb2; off = 106875; }
    else                 { s = wc2; off = 414075; }
    o[i] = split2(s[i - off]);
}

// ============================================================================
// SIMT fp32 GEMM (R3/R6 compute path) + coalesced flat A staging for MODE 1.
// MODE 0: conv over H (im2col gather).  MODE 1: semi-linear (contiguous rows).
// For MODE 1 set BK == K (KITER == 1) -> flat float4 staging path.
// ============================================================================
template<int MODE,int KH,int BM,int BN,int BK,int TM,int TN,int N,int K,int RELU,int ACCUM,int HOUT>
__global__ void __launch_bounds__((BM/TM)*(BN/TN), 2)
gemm(const float* __restrict__ A, const float* __restrict__ W,
     const float* __restrict__ bias, float* __restrict__ Out, __half2* __restrict__ hOut,
     int IH, int IW, int PH, int SP, int OW, int abstride)
{
    constexpr int NT    = (BM/TM)*(BN/TN);
    constexpr int KITER = (K + BK - 1) / BK;
    constexpr bool KG   = (K % BK) != 0;
    constexpr bool NG   = (N % BN) != 0;
    constexpr bool FLAT = (MODE == 1 && KITER == 1 && !KG);
    constexpr int ROWS  = (BM > NT) ? BM/NT : 1;
    constexpr int KSL   = (NT > BM) ? NT/BM : 1;
    constexpr int AJ    = BK / KSL;
    static_assert(BK % KSL == 0, "");
    static_assert(TN % 2 == 0, "");

    __shared__ __align__(16) float sA[BK][2*BM + 4];
    __shared__ __align__(16) float sB[BK][BN + 4];

    const int tid = threadIdx.x;
    const int m0  = blockIdx.x * BM;
    const int n0  = blockIdx.y * BN;

    const int a_k0 = (NT > BM) ? (tid / BM) : 0;
    const float* Abase[ROWS];
    int oh_[ROWS], aml[ROWS];
    const int IHW = IH * IW;
    if constexpr (!FLAT) {
#pragma unroll
        for (int r = 0; r < ROWS; r++) {
            const int ml = (NT >= BM) ? (tid % BM) : (tid + r * NT);
            aml[r] = ml;
            const int m = m0 + ml;
            const int b = m / SP;
            const int s = m - b * SP;
            if (MODE == 0) {
                const int oh = s / OW;
                oh_[r] = oh;
                Abase[r] = A + (long long)b * abstride + (s - oh * OW);
            } else {
                oh_[r] = 0;
                Abase[r] = A + (long long)b * abstride + (long long)s * K;
            }
        }
    }

    const int tn = tid % (BN/TN);
    const int tm = tid / (BN/TN);

    float2 acc[TM][TN/2];
#pragma unroll
    for (int i = 0; i < TM; i++)
#pragma unroll
        for (int j = 0; j < TN/2; j++) acc[i][j] = make_float2(0.f, 0.f);

    for (int kt = 0; kt < KITER; kt++) {
        const int k0 = kt * BK;
        // ---- stage A ----
        if constexpr (FLAT) {
            // block's A region is contiguous: coalesced float4 load + transpose
            const float* Ablk = A + (long long)m0 * K;
#pragma unroll
            for (int i4 = tid * 4; i4 < BM * K; i4 += NT * 4) {
                const float4 v = *(const float4*)(Ablk + i4);
#pragma unroll
                for (int e = 0; e < 4; e++) {
                    const int idx = i4 + e;
                    const int m = idx / K;
                    const int k = idx - m * K;
                    const float val = (&v.x)[e];
                    *(float2*)&sA[k][2*m] = make_float2(val, val);
                }
            }
        } else {
#pragma unroll
            for (int r = 0; r < ROWS; r++) {
#pragma unroll
                for (int j = 0; j < AJ; j++) {
                    const int kl = a_k0 + KSL * j;
                    const int k  = k0 + kl;
                    float v = 0.0f;
                    if (!KG || k < K) {
                        if (MODE == 0) {
                            const int ic = k / KH;
                            const int kh = k - ic * KH;
                            const int ih = oh_[r] + kh - PH;
                            if ((unsigned)ih < (unsigned)IH)
                                v = Abase[r][ic * IHW + ih * IW];
                        } else {
                            v = Abase[r][k];
                        }
                    }
                    *(float2*)&sA[kl][2 * aml[r]] = make_float2(v, v);
                }
            }
        }
        // ---- stage B ----
        constexpr int BTOT = BK * BN;
        constexpr int BIT  = (BTOT + NT - 1) / NT;
#pragma unroll
        for (int t = 0; t < BIT; t++) {
            const int idx = tid + t * NT;
            if (BTOT % NT == 0 || idx < BTOT) {
                const int kl = idx % BK;
                const int n  = idx / BK;
                const int k  = k0 + kl;
                const int nn = n0 + n;
                float v = 0.0f;
                if ((!KG || k < K) && (!NG || nn < N)) v = W[nn * K + k];
                sB[kl][n] = v;
            }
        }
        __syncthreads();

#pragma unroll
        for (int kk = 0; kk < BK; kk++) {
            float2 a2[TM], b2[TN/2];
            {
                const float4* pa = (const float4*)&sA[kk][2 * tm * TM];
#pragma unroll
                for (int q = 0; q < TM/2; q++) {
                    const float4 t4 = pa[q];
                    a2[2*q]   = make_float2(t4.x, t4.y);
                    a2[2*q+1] = make_float2(t4.z, t4.w);
                }
            }
            if constexpr (TN % 4 == 0) {
                const float4* pb = (const float4*)&sB[kk][tn * TN];
#pragma unroll
                for (int q = 0; q < TN/4; q++) {
                    const float4 t4 = pb[q];
                    b2[2*q]   = make_float2(t4.x, t4.y);
                    b2[2*q+1] = make_float2(t4.z, t4.w);
                }
            } else {
                const float2* pb = (const float2*)&sB[kk][tn * TN];
#pragma unroll
                for (int q = 0; q < TN/2; q++) b2[q] = pb[q];
            }
#pragma unroll
            for (int i = 0; i < TM; i++)
#pragma unroll
                for (int j = 0; j < TN/2; j++)
                    ffma2(acc[i][j], a2[i], b2[j]);
        }
        __syncthreads();
    }

#pragma unroll
    for (int i = 0; i < TM; i++) {
        const int m = m0 + tm * TM + i;
        const int b = m / SP;
        const int s = m - b * SP;
#pragma unroll
        for (int j = 0; j < TN/2; j++) {
#pragma unroll
            for (int h = 0; h < 2; h++) {
                const int n = n0 + tn * TN + 2*j + h;
                if (!NG || n < N) {
                    float v = (h ? acc[i][j].y : acc[i][j].x) + bias[n];
                    if (RELU) v = fmaxf(v, 0.0f);
                    long long o;
                    if (MODE == 0) o = (long long)b * (N * SP) + (long long)n * SP + s;
                    else           o = (long long)b * (SP * N) + (long long)s * N + n;
                    if (ACCUM) v += Out[o];
                    Out[o] = v;
                    if (HOUT) hOut[o] = split2(v);
                }
            }
        }
    }
}

// ============================================================================
// Tensor-core conv GEMM v3: pre-split half2 inputs, reg prefetch,
// double-buffered smem (one __syncthreads per k-tile).
// ============================================================================
__device__ __forceinline__ void mma16816(float* c, const uint32_t* a, const uint32_t* b) {
    asm volatile(
        "mma.sync.aligned.m16n8k16.row.col.f32.f16.f16.f32 "
        "{%0,%1,%2,%3}, {%4,%5,%6,%7}, {%8,%9}, {%0,%1,%2,%3};"
        : "+f"(c[0]), "+f"(c[1]), "+f"(c[2]), "+f"(c[3])
        : "r"(a[0]), "r"(a[1]), "r"(a[2]), "r"(a[3]), "r"(b[0]), "r"(b[1]));
}

template<int KH,int N,int K,int ACCUM,int HOUT,int NB>
__global__ void __launch_bounds__(128, 4)
tconv(const __half2* __restrict__ Ah, const __half2* __restrict__ Wh,
      const float* __restrict__ bias, float* __restrict__ Out, __half2* __restrict__ hOut,
      int IH, int IW, int PH, int SP, int OW, int abstride)
{
    constexpr int BM = 64, BN = 64, BK = 32;
    constexpr int KITER = (K + BK - 1) / BK;
    constexpr int PAD   = 38;
    __shared__ __align__(16) __half sAhi[2][BM][PAD];
    __shared__ __align__(16) __half sAlo[2][BM][PAD];
    __shared__ __align__(16) __half sBhi[2][BN][PAD];
    __shared__ __align__(16) __half sBlo[2][BN][PAD];

    const int tid  = threadIdx.x;
    const int nb   = (int)(blockIdx.x % NB);
    const int mb   = (int)(blockIdx.x / NB);
    const int m0   = mb * BM;
    const int n0   = nb * BN;
    const int IHW  = IH * IW;

    const int arow = tid & 63;
    const int ak0  = tid >> 6;
    const int am   = m0 + arow;
    const int ab   = am / SP;
    const int as   = am - ab * SP;
    const int aoh  = as / OW;
    const __half2* Abase = Ah + (long long)ab * abstride + (as - aoh * OW);

    const int bkl = tid & 31;
    const int bn0 = tid >> 5;

    const int warp = tid >> 5, lane = tid & 31;
    const int wm = (warp & 1) * 32;
    const int wn = (warp >> 1) * 32;
    const int gr = lane >> 2;
    const int gc = lane & 3;

    __half2 aR[16], bR[16];
    const __half2 Z2 = __float2half2_rn(0.0f);

    auto prefetch = [&](int kt) {
        const int k0 = kt * BK;
#pragma unroll
        for (int t = 0; t < 16; t++) {
            const int k = k0 + ak0 + 2 * t;
            __half2 v = Z2;
            if (K % BK == 0 || k < K) {
                const int ic = k / KH;
                const int kh = k - ic * KH;
                const int ih = aoh + kh - PH;
                if ((unsigned)ih < (unsigned)IH)
                    v = Abase[ic * IHW + ih * IW];
            }
            aR[t] = v;
        }
        const int kB = k0 + bkl;
#pragma unroll
        for (int t = 0; t < 16; t++) {
            const int nn = n0 + bn0 + 4 * t;
            __half2 v = Z2;
            if ((K % BK == 0 || kB < K) && (N % BN == 0 || nn < N))
                v = Wh[(long long)nn * K + kB];
            bR[t] = v;
        }
    };

    auto stage = [&](int p) {
#pragma unroll
        for (int t = 0; t < 16; t++) {
            const int kl = ak0 + 2 * t;
            sAhi[p][arow][kl] = __low2half(aR[t]);
            sAlo[p][arow][kl] = __high2half(aR[t]);
        }
#pragma unroll
        for (int t = 0; t < 16; t++) {
            const int nl = bn0 + 4 * t;
            sBhi[p][nl][bkl] = __low2half(bR[t]);
            sBlo[p][nl][bkl] = __high2half(bR[t]);
        }
    };

    float acc[2][4][4];
#pragma unroll
    for (int i = 0; i < 2; i++)
#pragma unroll
        for (int j = 0; j < 4; j++)
#pragma unroll
            for (int q = 0; q < 4; q++) acc[i][j][q] = 0.0f;

    auto compute = [&](int p) {
#pragma unroll
        for (int ck = 0; ck < BK / 16; ck++) {
            const int kb = ck * 16 + 2 * gc;
            uint32_t ahi[2][4], alo[2][4], bhi[4][2], blo[4][2];
#pragma unroll
            for (int ms = 0; ms < 2; ms++) {
                const int r0 = wm + ms * 16 + gr;
                ahi[ms][0] = *(const uint32_t*)&sAhi[p][r0    ][kb    ];
                ahi[ms][1] = *(const uint32_t*)&sAhi[p][r0 + 8][kb    ];
                ahi[ms][2] = *(const uint32_t*)&sAhi[p][r0    ][kb + 8];
                ahi[ms][3] = *(const uint32_t*)&sAhi[p][r0 + 8][kb + 8];
                alo[ms][0] = *(const uint32_t*)&sAlo[p][r0    ][kb    ];
                alo[ms][1] = *(const uint32_t*)&sAlo[p][r0 + 8][kb    ];
                alo[ms][2] = *(const uint32_t*)&sAlo[p][r0    ][kb + 8];
                alo[ms][3] = *(const uint32_t*)&sAlo[p][r0 + 8][kb + 8];
            }
#pragma unroll
            for (int ns = 0; ns < 4; ns++) {
                const int nr = wn + ns * 8 + gr;
                bhi[ns][0] = *(const uint32_t*)&sBhi[p][nr][kb    ];
                bhi[ns][1] = *(const uint32_t*)&sBhi[p][nr][kb + 8];
                blo[ns][0] = *(const uint32_t*)&sBlo[p][nr][kb    ];
                blo[ns][1] = *(const uint32_t*)&sBlo[p][nr][kb + 8];
            }
#pragma unroll
            for (int ms = 0; ms < 2; ms++)
#pragma unroll
                for (int ns = 0; ns < 4; ns++) {
                    mma16816(acc[ms][ns], ahi[ms], bhi[ns]);
                    mma16816(acc[ms][ns], ahi[ms], blo[ns]);
                    mma16816(acc[ms][ns], alo[ms], bhi[ns]);
                }
        }
    };

    prefetch(0);
    stage(0);
    __syncthreads();
    for (int kt = 0; kt < KITER; kt++) {
        if (kt + 1 < KITER) prefetch(kt + 1);
        compute(kt & 1);
        if (kt + 1 < KITER) {
            stage((kt + 1) & 1);
            __syncthreads();
        }
    }

#pragma unroll
    for (int ms = 0; ms < 2; ms++) {
        const int mr0 = m0 + wm + ms * 16 + gr;
#pragma unroll
        for (int half = 0; half < 2; half++) {
            const int m = mr0 + half * 8;
            const int b = m / SP;
            const int s = m - b * SP;
            const long long obase = (long long)b * (N * SP) + s;
#pragma unroll
            for (int ns = 0; ns < 4; ns++) {
                const int n = n0 + wn + ns * 8 + 2 * gc;
#pragma unroll
                for (int e = 0; e < 2; e++) {
                    const int nn = n + e;
                    if (N % BN == 0 || nn < N) {
                        float v = acc[ms][ns][half * 2 + e] + bias[nn];
                        const long long o = obase + (long long)nn * SP;
                        if (ACCUM) v += Out[o];
                        Out[o] = v;
                        if (HOUT) hOut[o] = split2(v);
                    }
                }
            }
        }
    }
}

// ---------------- host-side typed launchers ----------------
template<int KH,int BN,int BK,int TM,int TN,int N,int K,int ACCUM,int HOUT>
static void conv(const float* A, const float* W, const float* b, float* O, __half2* hO,
                 int IH, int IW, int PH)
{
    constexpr int BM = 128;
    const int OH = IH + 2*PH - KH + 1, OW = IW, SP = OH * OW;
    const long long M = (long long)BATCH * SP;
    dim3 g((unsigned)(M / BM), (N + BN - 1) / BN);
    gemm<0,KH,BM,BN,BK,TM,TN,N,K,0,ACCUM,HOUT><<<g, (BM/TM)*(BN/TN)>>>(
        A, W, b, O, hO, IH, IW, PH, SP, OW, (K/KH)*IH*IW);
}

template<int KH,int N,int K,int ACCUM,int HOUT>
static void tconv_l(const __half2* A, const __half2* W, const float* b, float* O,
                    __half2* hO, int IH, int IW, int PH)
{
    constexpr int NB = (N + 63) / 64;
    const int OH = IH + 2*PH - KH + 1, OW = IW, SP = OH * OW;
    const long long M = (long long)BATCH * SP;
    dim3 g((unsigned)((M / 64) * NB));
    tconv<KH,N,K,ACCUM,HOUT,NB><<<g, 128>>>(A, W, b, O, hO, IH, IW, PH, SP, OW, (K/KH)*IH*IW);
}

template<int BN,int BK,int TM,int TN,int N,int K,int RELU,int HOUT>
static void sl(const float* A, const float* W, const float* b, float* O, __half2* hO, int SP)
{
    constexpr int BM = 128;
    const long long M = (long long)BATCH * SP;
    dim3 g((unsigned)(M / BM), (N + BN - 1) / BN);
    gemm<1,1,BM,BN,BK,TM,TN,N,K,RELU,0,HOUT><<<g, (BM/TM)*(BN/TN)>>>(
        A, W, b, O, hO, 1, 1, 0, SP, 1, SP*K);
}

extern "C" void kernel_launch(void* const* d_in, const int* in_sizes, int n_in,
                              void* d_out, int out_size)
{
    (void)in_sizes; (void)n_in; (void)out_size;
    const float* x    = (const float*)d_in[0];
    const float* w0a  = (const float*)d_in[1];  const float* b0a  = (const float*)d_in[2];
    const float* wl0  = (const float*)d_in[3];  const float* bl0  = (const float*)d_in[4];
    const float* w0b  = (const float*)d_in[5];  const float* b0b  = (const float*)d_in[6];
    const float* w0c  = (const float*)d_in[7];  const float* b0c  = (const float*)d_in[8];
    const float* wr0  = (const float*)d_in[9];  const float* br0  = (const float*)d_in[10];
    const float* w1   = (const float*)d_in[11]; const float* b1   = (const float*)d_in[12];
    const float* wl1  = (const float*)d_in[13]; const float* bl1  = (const float*)d_in[14];
    const float* w2   = (const float*)d_in[15]; const float* b2   = (const float*)d_in[16];
    const float* wa   = (const float*)d_in[17]; const float* ba   = (const float*)d_in[18];
    const float* wra  = (const float*)d_in[19]; const float* bra  = (const float*)d_in[20];
    const float* w0   = (const float*)d_in[21]; const float* b0   = (const float*)d_in[22];
    const float* wl2  = (const float*)d_in[23]; const float* bl2  = (const float*)d_in[24];
    const float* w0b2 = (const float*)d_in[25]; const float* b0b2 = (const float*)d_in[26];
    const float* w0c2 = (const float*)d_in[27]; const float* b0c2 = (const float*)d_in[28];
    const float* wr02 = (const float*)d_in[29]; const float* br02 = (const float*)d_in[30];
    float* out = (float*)d_out;

    float *A, *Bb, *C, *x1, *x2;
    __half2 *hX, *hB, *hC, *hW;
    cudaGetSymbolAddress((void**)&A,  g_bufA);
    cudaGetSymbolAddress((void**)&Bb, g_bufB);
    cudaGetSymbolAddress((void**)&C,  g_bufC);
    cudaGetSymbolAddress((void**)&x1, g_x1);
    cudaGetSymbolAddress((void**)&x2, g_x2);
    cudaGetSymbolAddress((void**)&hX, g_hX);
    cudaGetSymbolAddress((void**)&hB, g_hB);
    cudaGetSymbolAddress((void**)&hC, g_hC);
    cudaGetSymbolAddress((void**)&hW, g_hW);

    // ---- weight pre-split (hi,lo) for the 6 heavy layers, one launch ----
    __half2* hw1   = hW;            // 3750
    __half2* hw2   = hW + 3750;     // 18750
    __half2* hwa   = hW + 22500;    // 9375
    __half2* hw0   = hW + 31875;    // 75000
    __half2* hw0b2 = hW + 106875;   // 307200
    __half2* hw0c2 = hW + 414075;   // 192000
    split_w6<<<(606075 + 255) / 256, 256>>>(w1, w2, wa, w0, w0b2, w0c2, hW);

    // ---- stage 0 ----
    conv<3,  8, 4, 8,2,   5,  3, 0,0>(x,  w0a,  b0a,  A,  nullptr, 5, 27, 1);
    sl  <32,27, 8,4,  18, 27, 1, 0  >(A,  wl0,  bl0,  Bb, nullptr, 25);       // relu (flat)
    conv<3, 32,15, 8,4,  25, 15, 0,0>(Bb, w0b,  b0b,  x1, nullptr, 5, 18, 1);
    sl  <32,27, 8,4,  18, 27, 0, 0  >(x,  wr0,  br0,  C,  nullptr, 5);        // (flat)
    conv<1, 32, 1, 8,4,  25,  1, 1,1>(C,  w0c,  b0c,  x1, hX,      5, 18, 0); // final x1 + half

    // ---- stage 1 ----
    tconv_l<2,  75,  50, 0,0>(hX, hw1, b1, A, nullptr, 5, 18, 0);
    sl  <16,18, 8,4,  10, 18, 1, 1  >(A,  wl1,  bl1,  Bb, hB, 300);           // relu + half (flat)
    tconv_l<2, 125, 150, 0,0>(hB, hw2, b2, x2, nullptr, 4, 10, 0);
    sl  <16,18, 8,4,  10, 18, 0, 1  >(x1, wra,  bra,  C,  hC, 125);           // + half (flat)
    tconv_l<3, 125,  75, 1,1>(hC, hwa, ba, x2, hX, 5, 10, 0);                 // += y, x2 + half

    // ---- stage 2 ----
    tconv_l<2, 300, 250, 0,0>(hX, hw0, b0, A, nullptr, 3, 10, 0);
    sl  < 8,10, 8,2,   5, 10, 1, 1  >(A,  wl2,  bl2,  Bb, hB, 600);           // relu + half (flat)
    tconv_l<2, 512, 600, 0,0>(hB, hw0b2, b0b2, out, nullptr, 2, 5, 0);
    sl  < 8,10, 8,2,   5, 10, 0, 1  >(x2, wr02, br02, C,  hC, 375);           // + half (flat)
    tconv_l<3, 512, 375, 1,0>(hC, hw0c2, b0c2, out, nullptr, 3, 5, 0);
}

// round 11
// speedup vs baseline: 1.6013x; 1.1767x over previous
#include <cuda_runtime.h>
#include <cuda_fp16.h>
#include <cstdint>

#define BATCH 16384

// ---------------- static scratch (device globals; no allocations) ----------------
__device__ float g_bufA[(long long)BATCH * 6000];
__device__ float g_bufB[(long long)BATCH * 3000];
__device__ float g_bufC[(long long)BATCH * 1875];
__device__ float g_x1 [(long long)BATCH * 2250];
__device__ float g_x2 [(long long)BATCH * 3750];
// half (hi,lo) interleaved planes for tensor-core consumers
__device__ __half2 g_hX[(long long)BATCH * 3750];
__device__ __half2 g_hB[(long long)BATCH * 3000];
__device__ __half2 g_hC[(long long)BATCH * 1875];
__device__ __half2 g_hW[606080];

__device__ __forceinline__ __half2 split2(float v) {
    const __half hi = __float2half_rn(v);
    return __halves2half2(hi, __float2half_rn(v - __half2float(hi)));
}

// Packed fp32x2 FMA (Blackwell FFMA2).
__device__ __forceinline__ void ffma2(float2& d, const float2& a, const float2& b) {
    unsigned long long& dd = reinterpret_cast<unsigned long long&>(d);
    const unsigned long long& aa = reinterpret_cast<const unsigned long long&>(a);
    const unsigned long long& bb = reinterpret_cast<const unsigned long long&>(b);
    asm("fma.rn.f32x2 %0, %1, %2, %0;" : "+l"(dd) : "l"(aa), "l"(bb));
}

// ---------------- weight pre-split (single launch, 6 weights) ----------------
__global__ void split_w6(const float* __restrict__ w1, const float* __restrict__ w2,
                         const float* __restrict__ wa, const float* __restrict__ w0,
                         const float* __restrict__ wb2, const float* __restrict__ wc2,
                         __half2* __restrict__ o)
{
    const int i = blockIdx.x * 256 + threadIdx.x;
    if (i >= 606075) return;
    const float* s; int off;
    if      (i <   3750) { s = w1;  off = 0; }
    else if (i <  22500) { s = w2;  off = 3750; }
    else if (i <  31875) { s = wa;  off = 22500; }
    else if (i < 106875) { s = w0;  off = 31875; }
    else if (i < 414075) { s = wb2; off = 106875; }
    else                 { s = wc2; off = 414075; }
    o[i] = split2(s[i - off]);
}

// ============================================================================
// Fused stage 0: x -> conv(w0a) -> sl(wl0)+relu -> conv(w0b); x -> sl(wr0) ->
// conv(w0c); x1 = sum. One CTA handles ITEMS batch items entirely in smem.
// Writes x1 (fp32) and hX (hi/lo half2) directly.
// ============================================================================
__global__ void __launch_bounds__(256)
stage0_fused(const float* __restrict__ X,
             const float* __restrict__ w0a, const float* __restrict__ b0a,
             const float* __restrict__ wl0, const float* __restrict__ bl0,
             const float* __restrict__ w0b, const float* __restrict__ b0b,
             const float* __restrict__ w0c, const float* __restrict__ b0c,
             const float* __restrict__ wr0, const float* __restrict__ br0,
             float* __restrict__ x1, __half2* __restrict__ hX)
{
    constexpr int ITEMS = 4;
    // weight offsets in sW
    constexpr int W0A = 0, B0A = 15, WL0 = 20, BL0 = 506, WR0 = 524, BR0 = 1010,
                  W0B = 1028, B0B = 1403, W0C = 1428, B0C = 1453, WTOT = 1478;
    constexpr int PITEM = 1352;                 // per-item smem block (floats)
    __shared__ float sm[WTOT + ITEMS * PITEM];  // ~27.5 KB

    const int tid = threadIdx.x;
    const long long base = (long long)blockIdx.x * ITEMS;

    // ---- stage weights ----
    for (int i = tid; i < WTOT; i += 256) {
        float v;
        if      (i < B0A) v = w0a[i - W0A];
        else if (i < WL0) v = b0a[i - B0A];
        else if (i < BL0) v = wl0[i - WL0];
        else if (i < WR0) v = bl0[i - BL0];
        else if (i < BR0) v = wr0[i - WR0];
        else if (i < W0B) v = br0[i - BR0];
        else if (i < B0B) v = w0b[i - W0B];
        else if (i < W0C) v = b0b[i - B0B];
        else if (i < B0C) v = w0c[i - W0C];
        else              v = b0c[i - B0C];
        sm[i] = v;
    }
    // ---- load x (ITEMS * 135 contiguous) ----
    for (int i = tid; i < ITEMS * 135; i += 256) {
        const int it = i / 135, j = i - it * 135;
        sm[WTOT + it * PITEM + j] = X[(base + it) * 135 + j];
    }
    __syncthreads();

    // ---- conv w0a: z0[oc][h][w], oc<5, h<5, w<27 (PH=1, KH=3) ----
    for (int i = tid; i < ITEMS * 675; i += 256) {
        const int it = i / 675, q = i - it * 675;
        const int oc = q / 135, hw = q - oc * 135;
        const int h = hw / 27, w = hw - h * 27;
        const float* xi = &sm[WTOT + it * PITEM];
        float v = sm[B0A + oc];
#pragma unroll
        for (int kh = 0; kh < 3; kh++) {
            const int ih = h + kh - 1;
            if ((unsigned)ih < 5u)
                v = fmaf(xi[ih * 27 + w], sm[W0A + oc * 3 + kh], v);
        }
        sm[WTOT + it * PITEM + 135 + q] = v;
    }
    __syncthreads();

    // ---- sl wl0 + relu: z1[rr][o], rr<25 (=(c,h)), o<18 ; sl wr0: y[h][o] ----
    for (int i = tid; i < ITEMS * (450 + 90); i += 256) {
        if (i < ITEMS * 450) {
            const int it = i / 450, q = i - it * 450;
            const int rr = q / 18, o = q - rr * 18;
            const float* z0 = &sm[WTOT + it * PITEM + 135 + rr * 27];
            float v = sm[BL0 + o];
            const float* wl = &sm[WL0 + o * 27];
#pragma unroll
            for (int w = 0; w < 27; w++) v = fmaf(z0[w], wl[w], v);
            sm[WTOT + it * PITEM + 810 + rr * 18 + o] = fmaxf(v, 0.0f);
        } else {
            const int j = i - ITEMS * 450;
            const int it = j / 90, q = j - it * 90;
            const int h = q / 18, o = q - h * 18;
            const float* xi = &sm[WTOT + it * PITEM + h * 27];
            float v = sm[BR0 + o];
            const float* wr = &sm[WR0 + o * 27];
#pragma unroll
            for (int w = 0; w < 27; w++) v = fmaf(xi[w], wr[w], v);
            sm[WTOT + it * PITEM + 1261 + q] = v;
        }
    }
    __syncthreads();

    // ---- conv w0b (PH=1,KH=3,IC=5 over z1) + w0c*y + write ----
    for (int i = tid; i < ITEMS * 2250; i += 256) {
        const int it = i / 2250, r = i - it * 2250;
        const int oc = r / 90, ho = r - oc * 90;
        const int h = ho / 18, o = ho - h * 18;
        const float* z1 = &sm[WTOT + it * PITEM + 810];
        float v = sm[B0B + oc];
#pragma unroll
        for (int ic = 0; ic < 5; ic++) {
#pragma unroll
            for (int kh = 0; kh < 3; kh++) {
                const int ih = h + kh - 1;
                if ((unsigned)ih < 5u)
                    v = fmaf(z1[(ic * 5 + ih) * 18 + o], sm[W0B + oc * 15 + ic * 3 + kh], v);
            }
        }
        const float y = sm[WTOT + it * PITEM + 1261 + h * 18 + o];
        v = fmaf(y, sm[W0C + oc], v) + sm[B0C + oc];
        const long long gidx = (base + it) * 2250 + r;
        x1[gidx] = v;
        hX[gidx] = split2(v);
    }
}

// ============================================================================
// SIMT fp32 GEMM (proven) + coalesced flat A staging for MODE 1.
// FOUT=0 skips the fp32 store (half-plane-only consumers).
// ============================================================================
template<int MODE,int KH,int BM,int BN,int BK,int TM,int TN,int N,int K,int RELU,int ACCUM,int HOUT,int FOUT>
__global__ void __launch_bounds__((BM/TM)*(BN/TN), 2)
gemm(const float* __restrict__ A, const float* __restrict__ W,
     const float* __restrict__ bias, float* __restrict__ Out, __half2* __restrict__ hOut,
     int IH, int IW, int PH, int SP, int OW, int abstride)
{
    constexpr int NT    = (BM/TM)*(BN/TN);
    constexpr int KITER = (K + BK - 1) / BK;
    constexpr bool KG   = (K % BK) != 0;
    constexpr bool NG   = (N % BN) != 0;
    constexpr bool FLAT = (MODE == 1 && KITER == 1 && !KG);
    constexpr int ROWS  = (BM > NT) ? BM/NT : 1;
    constexpr int KSL   = (NT > BM) ? NT/BM : 1;
    constexpr int AJ    = BK / KSL;
    static_assert(BK % KSL == 0, "");
    static_assert(TN % 2 == 0, "");

    __shared__ __align__(16) float sA[BK][2*BM + 4];
    __shared__ __align__(16) float sB[BK][BN + 4];

    const int tid = threadIdx.x;
    const int m0  = blockIdx.x * BM;
    const int n0  = blockIdx.y * BN;

    const int a_k0 = (NT > BM) ? (tid / BM) : 0;
    const float* Abase[ROWS];
    int oh_[ROWS], aml[ROWS];
    const int IHW = IH * IW;
    if constexpr (!FLAT) {
#pragma unroll
        for (int r = 0; r < ROWS; r++) {
            const int ml = (NT >= BM) ? (tid % BM) : (tid + r * NT);
            aml[r] = ml;
            const int m = m0 + ml;
            const int b = m / SP;
            const int s = m - b * SP;
            if (MODE == 0) {
                const int oh = s / OW;
                oh_[r] = oh;
                Abase[r] = A + (long long)b * abstride + (s - oh * OW);
            } else {
                oh_[r] = 0;
                Abase[r] = A + (long long)b * abstride + (long long)s * K;
            }
        }
    }

    const int tn = tid % (BN/TN);
    const int tm = tid / (BN/TN);

    float2 acc[TM][TN/2];
#pragma unroll
    for (int i = 0; i < TM; i++)
#pragma unroll
        for (int j = 0; j < TN/2; j++) acc[i][j] = make_float2(0.f, 0.f);

    for (int kt = 0; kt < KITER; kt++) {
        const int k0 = kt * BK;
        if constexpr (FLAT) {
            const float* Ablk = A + (long long)m0 * K;
#pragma unroll
            for (int i4 = tid * 4; i4 < BM * K; i4 += NT * 4) {
                const float4 v = *(const float4*)(Ablk + i4);
#pragma unroll
                for (int e = 0; e < 4; e++) {
                    const int idx = i4 + e;
                    const int m = idx / K;
                    const int k = idx - m * K;
                    const float val = (&v.x)[e];
                    *(float2*)&sA[k][2*m] = make_float2(val, val);
                }
            }
        } else {
#pragma unroll
            for (int r = 0; r < ROWS; r++) {
#pragma unroll
                for (int j = 0; j < AJ; j++) {
                    const int kl = a_k0 + KSL * j;
                    const int k  = k0 + kl;
                    float v = 0.0f;
                    if (!KG || k < K) {
                        if (MODE == 0) {
                            const int ic = k / KH;
                            const int kh = k - ic * KH;
                            const int ih = oh_[r] + kh - PH;
                            if ((unsigned)ih < (unsigned)IH)
                                v = Abase[r][ic * IHW + ih * IW];
                        } else {
                            v = Abase[r][k];
                        }
                    }
                    *(float2*)&sA[kl][2 * aml[r]] = make_float2(v, v);
                }
            }
        }
        constexpr int BTOT = BK * BN;
        constexpr int BIT  = (BTOT + NT - 1) / NT;
#pragma unroll
        for (int t = 0; t < BIT; t++) {
            const int idx = tid + t * NT;
            if (BTOT % NT == 0 || idx < BTOT) {
                const int kl = idx % BK;
                const int n  = idx / BK;
                const int k  = k0 + kl;
                const int nn = n0 + n;
                float v = 0.0f;
                if ((!KG || k < K) && (!NG || nn < N)) v = W[nn * K + k];
                sB[kl][n] = v;
            }
        }
        __syncthreads();

#pragma unroll
        for (int kk = 0; kk < BK; kk++) {
            float2 a2[TM], b2[TN/2];
            {
                const float4* pa = (const float4*)&sA[kk][2 * tm * TM];
#pragma unroll
                for (int q = 0; q < TM/2; q++) {
                    const float4 t4 = pa[q];
                    a2[2*q]   = make_float2(t4.x, t4.y);
                    a2[2*q+1] = make_float2(t4.z, t4.w);
                }
            }
            if constexpr (TN % 4 == 0) {
                const float4* pb = (const float4*)&sB[kk][tn * TN];
#pragma unroll
                for (int q = 0; q < TN/4; q++) {
                    const float4 t4 = pb[q];
                    b2[2*q]   = make_float2(t4.x, t4.y);
                    b2[2*q+1] = make_float2(t4.z, t4.w);
                }
            } else {
                const float2* pb = (const float2*)&sB[kk][tn * TN];
#pragma unroll
                for (int q = 0; q < TN/2; q++) b2[q] = pb[q];
            }
#pragma unroll
            for (int i = 0; i < TM; i++)
#pragma unroll
                for (int j = 0; j < TN/2; j++)
                    ffma2(acc[i][j], a2[i], b2[j]);
        }
        __syncthreads();
    }

#pragma unroll
    for (int i = 0; i < TM; i++) {
        const int m = m0 + tm * TM + i;
        const int b = m / SP;
        const int s = m - b * SP;
#pragma unroll
        for (int j = 0; j < TN/2; j++) {
#pragma unroll
            for (int h = 0; h < 2; h++) {
                const int n = n0 + tn * TN + 2*j + h;
                if (!NG || n < N) {
                    float v = (h ? acc[i][j].y : acc[i][j].x) + bias[n];
                    if (RELU) v = fmaxf(v, 0.0f);
                    long long o;
                    if (MODE == 0) o = (long long)b * (N * SP) + (long long)n * SP + s;
                    else           o = (long long)b * (SP * N) + (long long)s * N + n;
                    if (ACCUM) v += Out[o];
                    if (FOUT) Out[o] = v;
                    if (HOUT) hOut[o] = split2(v);
                }
            }
        }
    }
}

// ============================================================================
// Tensor-core conv GEMM v3 (R9, proven): pre-split half2, reg prefetch,
// double-buffered smem.
// ============================================================================
__device__ __forceinline__ void mma16816(float* c, const uint32_t* a, const uint32_t* b) {
    asm volatile(
        "mma.sync.aligned.m16n8k16.row.col.f32.f16.f16.f32 "
        "{%0,%1,%2,%3}, {%4,%5,%6,%7}, {%8,%9}, {%0,%1,%2,%3};"
        : "+f"(c[0]), "+f"(c[1]), "+f"(c[2]), "+f"(c[3])
        : "r"(a[0]), "r"(a[1]), "r"(a[2]), "r"(a[3]), "r"(b[0]), "r"(b[1]));
}

template<int KH,int N,int K,int ACCUM,int HOUT,int NB>
__global__ void __launch_bounds__(128, 4)
tconv(const __half2* __restrict__ Ah, const __half2* __restrict__ Wh,
      const float* __restrict__ bias, float* __restrict__ Out, __half2* __restrict__ hOut,
      int IH, int IW, int PH, int SP, int OW, int abstride)
{
    constexpr int BM = 64, BN = 64, BK = 32;
    constexpr int KITER = (K + BK - 1) / BK;
    constexpr int PAD   = 38;
    __shared__ __align__(16) __half sAhi[2][BM][PAD];
    __shared__ __align__(16) __half sAlo[2][BM][PAD];
    __shared__ __align__(16) __half sBhi[2][BN][PAD];
    __shared__ __align__(16) __half sBlo[2][BN][PAD];

    const int tid  = threadIdx.x;
    const int nb   = (int)(blockIdx.x % NB);
    const int mb   = (int)(blockIdx.x / NB);
    const int m0   = mb * BM;
    const int n0   = nb * BN;
    const int IHW  = IH * IW;

    const int arow = tid & 63;
    const int ak0  = tid >> 6;
    const int am   = m0 + arow;
    const int ab   = am / SP;
    const int as   = am - ab * SP;
    const int aoh  = as / OW;
    const __half2* Abase = Ah + (long long)ab * abstride + (as - aoh * OW);

    const int bkl = tid & 31;
    const int bn0 = tid >> 5;

    const int warp = tid >> 5, lane = tid & 31;
    const int wm = (warp & 1) * 32;
    const int wn = (warp >> 1) * 32;
    const int gr = lane >> 2;
    const int gc = lane & 3;

    __half2 aR[16], bR[16];
    const __half2 Z2 = __float2half2_rn(0.0f);

    auto prefetch = [&](int kt) {
        const int k0 = kt * BK;
#pragma unroll
        for (int t = 0; t < 16; t++) {
            const int k = k0 + ak0 + 2 * t;
            __half2 v = Z2;
            if (K % BK == 0 || k < K) {
                const int ic = k / KH;
                const int kh = k - ic * KH;
                const int ih = aoh + kh - PH;
                if ((unsigned)ih < (unsigned)IH)
                    v = Abase[ic * IHW + ih * IW];
            }
            aR[t] = v;
        }
        const int kB = k0 + bkl;
#pragma unroll
        for (int t = 0; t < 16; t++) {
            const int nn = n0 + bn0 + 4 * t;
            __half2 v = Z2;
            if ((K % BK == 0 || kB < K) && (N % BN == 0 || nn < N))
                v = Wh[(long long)nn * K + kB];
            bR[t] = v;
        }
    };

    auto stage = [&](int p) {
#pragma unroll
        for (int t = 0; t < 16; t++) {
            const int kl = ak0 + 2 * t;
            sAhi[p][arow][kl] = __low2half(aR[t]);
            sAlo[p][arow][kl] = __high2half(aR[t]);
        }
#pragma unroll
        for (int t = 0; t < 16; t++) {
            const int nl = bn0 + 4 * t;
            sBhi[p][nl][bkl] = __low2half(bR[t]);
            sBlo[p][nl][bkl] = __high2half(bR[t]);
        }
    };

    float acc[2][4][4];
#pragma unroll
    for (int i = 0; i < 2; i++)
#pragma unroll
        for (int j = 0; j < 4; j++)
#pragma unroll
            for (int q = 0; q < 4; q++) acc[i][j][q] = 0.0f;

    auto compute = [&](int p) {
#pragma unroll
        for (int ck = 0; ck < BK / 16; ck++) {
            const int kb = ck * 16 + 2 * gc;
            uint32_t ahi[2][4], alo[2][4], bhi[4][2], blo[4][2];
#pragma unroll
            for (int ms = 0; ms < 2; ms++) {
                const int r0 = wm + ms * 16 + gr;
                ahi[ms][0] = *(const uint32_t*)&sAhi[p][r0    ][kb    ];
                ahi[ms][1] = *(const uint32_t*)&sAhi[p][r0 + 8][kb    ];
                ahi[ms][2] = *(const uint32_t*)&sAhi[p][r0    ][kb + 8];
                ahi[ms][3] = *(const uint32_t*)&sAhi[p][r0 + 8][kb + 8];
                alo[ms][0] = *(const uint32_t*)&sAlo[p][r0    ][kb    ];
                alo[ms][1] = *(const uint32_t*)&sAlo[p][r0 + 8][kb    ];
                alo[ms][2] = *(const uint32_t*)&sAlo[p][r0    ][kb + 8];
                alo[ms][3] = *(const uint32_t*)&sAlo[p][r0 + 8][kb + 8];
            }
#pragma unroll
            for (int ns = 0; ns < 4; ns++) {
                const int nr = wn + ns * 8 + gr;
                bhi[ns][0] = *(const uint32_t*)&sBhi[p][nr][kb    ];
                bhi[ns][1] = *(const uint32_t*)&sBhi[p][nr][kb + 8];
                blo[ns][0] = *(const uint32_t*)&sBlo[p][nr][kb    ];
                blo[ns][1] = *(const uint32_t*)&sBlo[p][nr][kb + 8];
            }
#pragma unroll
            for (int ms = 0; ms < 2; ms++)
#pragma unroll
                for (int ns = 0; ns < 4; ns++) {
                    mma16816(acc[ms][ns], ahi[ms], bhi[ns]);
                    mma16816(acc[ms][ns], ahi[ms], blo[ns]);
                    mma16816(acc[ms][ns], alo[ms], bhi[ns]);
                }
        }
    };

    prefetch(0);
    stage(0);
    __syncthreads();
    for (int kt = 0; kt < KITER; kt++) {
        if (kt + 1 < KITER) prefetch(kt + 1);
        compute(kt & 1);
        if (kt + 1 < KITER) {
            stage((kt + 1) & 1);
            __syncthreads();
        }
    }

#pragma unroll
    for (int ms = 0; ms < 2; ms++) {
        const int mr0 = m0 + wm + ms * 16 + gr;
#pragma unroll
        for (int half = 0; half < 2; half++) {
            const int m = mr0 + half * 8;
            const int b = m / SP;
            const int s = m - b * SP;
            const long long obase = (long long)b * (N * SP) + s;
#pragma unroll
            for (int ns = 0; ns < 4; ns++) {
                const int n = n0 + wn + ns * 8 + 2 * gc;
#pragma unroll
                for (int e = 0; e < 2; e++) {
                    const int nn = n + e;
                    if (N % BN == 0 || nn < N) {
                        float v = acc[ms][ns][half * 2 + e] + bias[nn];
                        const long long o = obase + (long long)nn * SP;
                        if (ACCUM) v += Out[o];
                        Out[o] = v;
                        if (HOUT) hOut[o] = split2(v);
                    }
                }
            }
        }
    }
}

// ---------------- host-side typed launchers ----------------
template<int KH,int BN,int BK,int TM,int TN,int N,int K,int ACCUM,int HOUT>
static void conv(const float* A, const float* W, const float* b, float* O, __half2* hO,
                 int IH, int IW, int PH)
{
    constexpr int BM = 128;
    const int OH = IH + 2*PH - KH + 1, OW = IW, SP = OH * OW;
    const long long M = (long long)BATCH * SP;
    dim3 g((unsigned)(M / BM), (N + BN - 1) / BN);
    gemm<0,KH,BM,BN,BK,TM,TN,N,K,0,ACCUM,HOUT,1><<<g, (BM/TM)*(BN/TN)>>>(
        A, W, b, O, hO, IH, IW, PH, SP, OW, (K/KH)*IH*IW);
}

template<int KH,int N,int K,int ACCUM,int HOUT>
static void tconv_l(const __half2* A, const __half2* W, const float* b, float* O,
                    __half2* hO, int IH, int IW, int PH)
{
    constexpr int NB = (N + 63) / 64;
    const int OH = IH + 2*PH - KH + 1, OW = IW, SP = OH * OW;
    const long long M = (long long)BATCH * SP;
    dim3 g((unsigned)((M / 64) * NB));
    tconv<KH,N,K,ACCUM,HOUT,NB><<<g, 128>>>(A, W, b, O, hO, IH, IW, PH, SP, OW, (K/KH)*IH*IW);
}

template<int BN,int BK,int TM,int TN,int N,int K,int RELU,int HOUT,int FOUT>
static void sl(const float* A, const float* W, const float* b, float* O, __half2* hO, int SP)
{
    constexpr int BM = 128;
    const long long M = (long long)BATCH * SP;
    dim3 g((unsigned)(M / BM), (N + BN - 1) / BN);
    gemm<1,1,BM,BN,BK,TM,TN,N,K,RELU,0,HOUT,FOUT><<<g, (BM/TM)*(BN/TN)>>>(
        A, W, b, O, hO, 1, 1, 0, SP, 1, SP*K);
}

extern "C" void kernel_launch(void* const* d_in, const int* in_sizes, int n_in,
                              void* d_out, int out_size)
{
    (void)in_sizes; (void)n_in; (void)out_size;
    const float* x    = (const float*)d_in[0];
    const float* w0a  = (const float*)d_in[1];  const float* b0a  = (const float*)d_in[2];
    const float* wl0  = (const float*)d_in[3];  const float* bl0  = (const float*)d_in[4];
    const float* w0b  = (const float*)d_in[5];  const float* b0b  = (const float*)d_in[6];
    const float* w0c  = (const float*)d_in[7];  const float* b0c  = (const float*)d_in[8];
    const float* wr0  = (const float*)d_in[9];  const float* br0  = (const float*)d_in[10];
    const float* w1   = (const float*)d_in[11]; const float* b1   = (const float*)d_in[12];
    const float* wl1  = (const float*)d_in[13]; const float* bl1  = (const float*)d_in[14];
    const float* w2   = (const float*)d_in[15]; const float* b2   = (const float*)d_in[16];
    const float* wa   = (const float*)d_in[17]; const float* ba   = (const float*)d_in[18];
    const float* wra  = (const float*)d_in[19]; const float* bra  = (const float*)d_in[20];
    const float* w0   = (const float*)d_in[21]; const float* b0   = (const float*)d_in[22];
    const float* wl2  = (const float*)d_in[23]; const float* bl2  = (const float*)d_in[24];
    const float* w0b2 = (const float*)d_in[25]; const float* b0b2 = (const float*)d_in[26];
    const float* w0c2 = (const float*)d_in[27]; const float* b0c2 = (const float*)d_in[28];
    const float* wr02 = (const float*)d_in[29]; const float* br02 = (const float*)d_in[30];
    float* out = (float*)d_out;

    float *A, *Bb, *C, *x1, *x2;
    __half2 *hX, *hB, *hC, *hW;
    cudaGetSymbolAddress((void**)&A,  g_bufA);
    cudaGetSymbolAddress((void**)&Bb, g_bufB);
    cudaGetSymbolAddress((void**)&C,  g_bufC);
    cudaGetSymbolAddress((void**)&x1, g_x1);
    cudaGetSymbolAddress((void**)&x2, g_x2);
    cudaGetSymbolAddress((void**)&hX, g_hX);
    cudaGetSymbolAddress((void**)&hB, g_hB);
    cudaGetSymbolAddress((void**)&hC, g_hC);
    cudaGetSymbolAddress((void**)&hW, g_hW);

    // ---- weight pre-split (hi,lo) for the 6 heavy layers, one launch ----
    __half2* hw1   = hW;            // 3750
    __half2* hw2   = hW + 3750;     // 18750
    __half2* hwa   = hW + 22500;    // 9375
    __half2* hw0   = hW + 31875;    // 75000
    __half2* hw0b2 = hW + 106875;   // 307200
    __half2* hw0c2 = hW + 414075;   // 192000
    split_w6<<<(606075 + 255) / 256, 256>>>(w1, w2, wa, w0, w0b2, w0c2, hW);

    // ---- stage 0: single fused kernel -> x1 + hX ----
    stage0_fused<<<BATCH / 4, 256>>>(x, w0a, b0a, wl0, bl0, w0b, b0b,
                                     w0c, b0c, wr0, br0, x1, hX);

    // ---- stage 1 ----
    tconv_l<2,  75,  50, 0,0>(hX, hw1, b1, A, nullptr, 5, 18, 0);
    sl  <16,18, 8,4,  10, 18, 1, 1, 0>(A,  wl1,  bl1,  Bb, hB, 300);  // relu, half only
    tconv_l<2, 125, 150, 0,0>(hB, hw2, b2, x2, nullptr, 4, 10, 0);
    sl  <16,18, 8,4,  10, 18, 0, 1, 0>(x1, wra,  bra,  C,  hC, 125);  // half only
    tconv_l<3, 125,  75, 1,1>(hC, hwa, ba, x2, hX, 5, 10, 0);         // += y, x2 + half

    // ---- stage 2 ----
    tconv_l<2, 300, 250, 0,0>(hX, hw0, b0, A, nullptr, 3, 10, 0);
    sl  < 8,10, 8,2,   5, 10, 1, 1, 0>(A,  wl2,  bl2,  Bb, hB, 600);  // relu, half only
    tconv_l<2, 512, 600, 0,0>(hB, hw0b2, b0b2, out, nullptr, 2, 5, 0);
    sl  < 8,10, 8,2,   5, 10, 0, 1, 0>(x2, wr02, br02, C,  hC, 375);  // half only
    tconv_l<3, 512, 375, 1,0>(hC, hw0c2, b0c2, out, nullptr, 3, 5, 0);
}